// round 3
// baseline (speedup 1.0000x reference)
#include <cuda_runtime.h>

// ---------------------------------------------------------------------------
// DistGAT: 2-layer GAT.
//   L1: fs1 = x @ W1 [100000,512] (+fused el/er); edge-softmax graph1; agg -> relu -> h1
//   L2: fs2 = h1 @ W2 [25000,76]; el/er; edge-softmax graph2; agg -> +b2 -> mean heads
// ---------------------------------------------------------------------------

#define N0c   100000
#define N1c   25000
#define N2c   5000
#define E1c   800000
#define E2c   160000
#define INc   1024
#define F1c   512     // H*HID
#define F2c   76      // H*C
#define HIDc  128
#define Cc    19
#define NEG   0.2f

// -------------------- device scratch (static, allocation-free) --------------
__device__ float g_fs1[(size_t)N0c * F1c];   // ~205 MB
__device__ float g_el1[(size_t)N0c * 4];
__device__ float g_er1[(size_t)N1c * 4];
__device__ float g_h1 [(size_t)N1c * F1c];
__device__ float g_fs2[(size_t)N1c * F2c];
__device__ float g_el2[(size_t)N1c * 4];
__device__ float g_er2[(size_t)N2c * 4];
__device__ int   g_deg1[N1c], g_off1[N1c + 1], g_pos1[N1c], g_esrc1[E1c];
__device__ int   g_deg2[N2c], g_off2[N2c + 1], g_pos2[N2c], g_esrc2[E2c];

// -------------------- graph CSR build ---------------------------------------
__global__ void zero_kernel() {
    int i = blockIdx.x * blockDim.x + threadIdx.x;
    if (i < N1c) g_deg1[i] = 0;
    if (i < N2c) g_deg2[i] = 0;
}

__global__ void count_kernel(const int* __restrict__ dst, int n, int which) {
    int i = blockIdx.x * blockDim.x + threadIdx.x;
    if (i < n) {
        if (which) atomicAdd(&g_deg2[dst[i]], 1);
        else       atomicAdd(&g_deg1[dst[i]], 1);
    }
}

__global__ void scan_kernel(int n, int which) {
    __shared__ int sh[1024];
    __shared__ int carry;
    int* deg = which ? g_deg2 : g_deg1;
    int* off = which ? g_off2 : g_off1;
    int* pos = which ? g_pos2 : g_pos1;
    int t = threadIdx.x;
    if (t == 0) carry = 0;
    __syncthreads();
    for (int base = 0; base < n; base += 1024) {
        int i = base + t;
        int v = (i < n) ? deg[i] : 0;
        int incl = v;
        sh[t] = v;
        __syncthreads();
        for (int s = 1; s < 1024; s <<= 1) {
            int add = (t >= s) ? sh[t - s] : 0;
            __syncthreads();
            incl += add;
            sh[t] = incl;
            __syncthreads();
        }
        int c = carry;
        if (i < n) { off[i] = incl - v + c; pos[i] = incl - v + c; }
        int total = sh[1023];
        __syncthreads();
        if (t == 0) carry = c + total;
        __syncthreads();
    }
    if (t == 0) off[n] = carry;
}

// stores the SOURCE NODE ID per CSR slot (not the edge index) — removes one
// level of random indirection in the aggregation hot loops.
__global__ void scatter_kernel(const int* __restrict__ dst, const int* __restrict__ src,
                               int n, int which) {
    int i = blockIdx.x * blockDim.x + threadIdx.x;
    if (i < n) {
        int s = src[i];
        if (which) { int p = atomicAdd(&g_pos2[dst[i]], 1); g_esrc2[p] = s; }
        else       { int p = atomicAdd(&g_pos1[dst[i]], 1); g_esrc1[p] = s; }
    }
}

// -------------------- GEMM1: fs1 = x @ W1  (M=100000, K=1024, N=512) --------
// 128x128 block tile, BK=16, 256 threads, 8x8 microtile as f32x2 pairs.
// blockIdx.y == head h (HID==128 == column tile), so the el1/er1 attention
// projections for head h are fully reducible inside this block's epilogue.
__global__ __launch_bounds__(256) void gemm1_kernel(const float* __restrict__ A,
                                                    const float* __restrict__ B,
                                                    const float* __restrict__ al,
                                                    const float* __restrict__ ar) {
    __shared__ float As[16][132];   // [k][m], padded to kill store conflicts
    __shared__ float Bs[16][128];   // [k][n]
    const int tid = threadIdx.x;
    const int bm = blockIdx.x * 128;
    const int h  = blockIdx.y;      // head index; col tile = h*128
    const int bn = h * 128;
    const int tx = tid & 15;
    const int ty = tid >> 4;

    const int qa0 = tid * 2, qa1 = qa0 + 1;
    const int arw0 = qa0 >> 2, ac0 = (qa0 & 3) << 2;   // A: 4 float4 per 16-wide row
    const int arw1 = qa1 >> 2, ac1 = (qa1 & 3) << 2;
    const int brw0 = qa0 >> 5, bc0 = (qa0 & 31) << 2;  // B: 32 float4 per 128-wide row
    const int brw1 = qa1 >> 5, bc1 = (qa1 & 31) << 2;
    const int row0 = bm + arw0;
    const int row1 = bm + arw1;

    unsigned long long acc[8][4];
#pragma unroll
    for (int m = 0; m < 8; m++)
#pragma unroll
        for (int j = 0; j < 4; j++) acc[m][j] = 0ULL;

    float4 va = make_float4(0.f, 0.f, 0.f, 0.f), vb = va, w0 = va, w1 = va;
    if (row0 < N0c) va = *(const float4*)(A + (size_t)row0 * INc + ac0);
    if (row1 < N0c) vb = *(const float4*)(A + (size_t)row1 * INc + ac1);
    w0 = *(const float4*)(B + (size_t)brw0 * F1c + bn + bc0);
    w1 = *(const float4*)(B + (size_t)brw1 * F1c + bn + bc1);

    for (int k0 = 0; k0 < INc; k0 += 16) {
        As[ac0 + 0][arw0] = va.x; As[ac0 + 1][arw0] = va.y;
        As[ac0 + 2][arw0] = va.z; As[ac0 + 3][arw0] = va.w;
        As[ac1 + 0][arw1] = vb.x; As[ac1 + 1][arw1] = vb.y;
        As[ac1 + 2][arw1] = vb.z; As[ac1 + 3][arw1] = vb.w;
        *(float4*)&Bs[brw0][bc0] = w0;
        *(float4*)&Bs[brw1][bc1] = w1;
        __syncthreads();

        // prefetch next k-tile into registers while computing this one
        int kn = k0 + 16;
        va = make_float4(0.f, 0.f, 0.f, 0.f); vb = va; w0 = va; w1 = va;
        if (kn < INc) {
            if (row0 < N0c) va = *(const float4*)(A + (size_t)row0 * INc + kn + ac0);
            if (row1 < N0c) vb = *(const float4*)(A + (size_t)row1 * INc + kn + ac1);
            w0 = *(const float4*)(B + (size_t)(kn + brw0) * F1c + bn + bc0);
            w1 = *(const float4*)(B + (size_t)(kn + brw1) * F1c + bn + bc1);
        }

#pragma unroll
        for (int k = 0; k < 16; k++) {
            float a[8];
            *(float4*)&a[0] = *(const float4*)&As[k][ty * 8];
            *(float4*)&a[4] = *(const float4*)&As[k][ty * 8 + 4];
            ulonglong2 u0 = *(const ulonglong2*)&Bs[k][tx * 8];
            ulonglong2 u1 = *(const ulonglong2*)&Bs[k][tx * 8 + 4];
            unsigned long long bq0 = u0.x, bq1 = u0.y, bq2 = u1.x, bq3 = u1.y;
#pragma unroll
            for (int m = 0; m < 8; m++) {
                unsigned long long ap;
                asm("mov.b64 %0, {%1, %1};" : "=l"(ap) : "r"(__float_as_uint(a[m])));
                asm("fma.rn.f32x2 %0, %1, %2, %0;" : "+l"(acc[m][0]) : "l"(ap), "l"(bq0));
                asm("fma.rn.f32x2 %0, %1, %2, %0;" : "+l"(acc[m][1]) : "l"(ap), "l"(bq1));
                asm("fma.rn.f32x2 %0, %1, %2, %0;" : "+l"(acc[m][2]) : "l"(ap), "l"(bq2));
                asm("fma.rn.f32x2 %0, %1, %2, %0;" : "+l"(acc[m][3]) : "l"(ap), "l"(bq3));
            }
        }
        __syncthreads();
    }

    // attention weights for this thread's 8 columns of head h
    float alv[8], arv[8];
#pragma unroll
    for (int j = 0; j < 8; j++) {
        alv[j] = al[h * HIDc + tx * 8 + j];
        arv[j] = ar[h * HIDc + tx * 8 + j];
    }

#pragma unroll
    for (int m = 0; m < 8; m++) {
        int row = bm + ty * 8 + m;
        float c[8];
#pragma unroll
        for (int j = 0; j < 4; j++) {
            c[2 * j]     = __uint_as_float((unsigned int)(acc[m][j] & 0xffffffffULL));
            c[2 * j + 1] = __uint_as_float((unsigned int)(acc[m][j] >> 32));
        }
        if (row < N0c) {
            float* cp = g_fs1 + (size_t)row * F1c + bn + tx * 8;
            *(float4*)(cp)     = *(float4*)&c[0];
            *(float4*)(cp + 4) = *(float4*)&c[4];
        }
        // fused attention projections: reduce this thread's 8-col partial dot
        // across the 16 tx-lanes (xor offsets < 16 stay within the half-warp).
        float pel = 0.f, per = 0.f;
#pragma unroll
        for (int j = 0; j < 8; j++) {
            pel = fmaf(c[j], alv[j], pel);
            per = fmaf(c[j], arv[j], per);
        }
#pragma unroll
        for (int o = 8; o; o >>= 1) {
            pel += __shfl_xor_sync(0xffffffffu, pel, o);
            per += __shfl_xor_sync(0xffffffffu, per, o);
        }
        if (tx == 0 && row < N0c) {
            g_el1[(size_t)row * 4 + h] = pel;
            if (row < N1c) g_er1[(size_t)row * 4 + h] = per;
        }
    }
}

// -------------------- block reductions --------------------------------------
__device__ __forceinline__ float bredmax(float v, float* sh, int t) {
    sh[t] = v; __syncthreads();
#pragma unroll
    for (int s = 64; s > 0; s >>= 1) { if (t < s) sh[t] = fmaxf(sh[t], sh[t + s]); __syncthreads(); }
    float r = sh[0]; __syncthreads(); return r;
}
__device__ __forceinline__ float bredsum(float v, float* sh, int t) {
    sh[t] = v; __syncthreads();
#pragma unroll
    for (int s = 64; s > 0; s >>= 1) { if (t < s) sh[t] = sh[t] + sh[t + s]; __syncthreads(); }
    float r = sh[0]; __syncthreads(); return r;
}

// -------------------- layer-1 edge softmax + aggregation + relu -------------
// one 128-thread block per dst node; thread t owns feature t of all 4 heads
__global__ __launch_bounds__(128) void agg1_kernel(const float* __restrict__ b1) {
    const int d = blockIdx.x, t = threadIdx.x;
    __shared__ int    sh_src[128];
    __shared__ float4 sh_ex[128];
    __shared__ float  sh_red[128];
    const int beg = g_off1[d];
    const int deg = g_off1[d + 1] - beg;
    float4 er = *(const float4*)(g_er1 + (size_t)d * 4);

    float m0 = -1e30f, m1 = -1e30f, m2 = -1e30f, m3 = -1e30f;
    for (int i = t; i < deg; i += 128) {
        int s = g_esrc1[beg + i];
        float4 el = *(const float4*)(g_el1 + (size_t)s * 4);
        float q;
        q = el.x + er.x; q = (q > 0.f) ? q : NEG * q; m0 = fmaxf(m0, q);
        q = el.y + er.y; q = (q > 0.f) ? q : NEG * q; m1 = fmaxf(m1, q);
        q = el.z + er.z; q = (q > 0.f) ? q : NEG * q; m2 = fmaxf(m2, q);
        q = el.w + er.w; q = (q > 0.f) ? q : NEG * q; m3 = fmaxf(m3, q);
    }
    m0 = bredmax(m0, sh_red, t); m1 = bredmax(m1, sh_red, t);
    m2 = bredmax(m2, sh_red, t); m3 = bredmax(m3, sh_red, t);

    float a0 = 0.f, a1 = 0.f, a2 = 0.f, a3 = 0.f;
    float s0 = 0.f, s1 = 0.f, s2 = 0.f, s3 = 0.f;
    for (int base = 0; base < deg; base += 128) {
        int len = min(128, deg - base);
        if (t < len) {
            int s = g_esrc1[beg + base + t];
            float4 el = *(const float4*)(g_el1 + (size_t)s * 4);
            float4 ex; float q;
            q = el.x + er.x; q = (q > 0.f) ? q : NEG * q; ex.x = __expf(q - m0); s0 += ex.x;
            q = el.y + er.y; q = (q > 0.f) ? q : NEG * q; ex.y = __expf(q - m1); s1 += ex.y;
            q = el.z + er.z; q = (q > 0.f) ? q : NEG * q; ex.z = __expf(q - m2); s2 += ex.z;
            q = el.w + er.w; q = (q > 0.f) ? q : NEG * q; ex.w = __expf(q - m3); s3 += ex.w;
            sh_src[t] = s; sh_ex[t] = ex;
        }
        __syncthreads();
#pragma unroll 4
        for (int i = 0; i < len; i++) {
            const float* r = g_fs1 + (size_t)sh_src[i] * F1c + t;
            float4 ex = sh_ex[i];
            a0 = fmaf(ex.x, r[0],   a0);
            a1 = fmaf(ex.y, r[128], a1);
            a2 = fmaf(ex.z, r[256], a2);
            a3 = fmaf(ex.w, r[384], a3);
        }
        __syncthreads();
    }
    s0 = bredsum(s0, sh_red, t); s1 = bredsum(s1, sh_red, t);
    s2 = bredsum(s2, sh_red, t); s3 = bredsum(s3, sh_red, t);
    float i0 = (deg > 0) ? 1.f / s0 : 0.f;
    float i1 = (deg > 0) ? 1.f / s1 : 0.f;
    float i2 = (deg > 0) ? 1.f / s2 : 0.f;
    float i3 = (deg > 0) ? 1.f / s3 : 0.f;
    size_t o = (size_t)d * F1c + t;
    g_h1[o +   0] = fmaxf(fmaf(a0, i0, b1[t +   0]), 0.f);
    g_h1[o + 128] = fmaxf(fmaf(a1, i1, b1[t + 128]), 0.f);
    g_h1[o + 256] = fmaxf(fmaf(a2, i2, b1[t + 256]), 0.f);
    g_h1[o + 384] = fmaxf(fmaf(a3, i3, b1[t + 384]), 0.f);
}

// -------------------- GEMM2: fs2 = h1 @ W2  (25000 x 512 x 76) --------------
// 64 rows/block (8 warps x 8 rows), K staged through smem in 128-chunks;
// W2 values register-reused across the warp's 8 rows.
__global__ __launch_bounds__(256) void gemm2_kernel(const float* __restrict__ W2) {
    __shared__ float sW[128 * F2c];   // 38 KB
    const int tid = threadIdx.x;
    const int l = tid & 31;
    const int w = tid >> 5;
    const int row0 = blockIdx.x * 64 + w * 8;

    float a0[8], a1[8], a2[8];
#pragma unroll
    for (int r = 0; r < 8; r++) { a0[r] = 0.f; a1[r] = 0.f; a2[r] = 0.f; }

    for (int kc = 0; kc < F1c; kc += 128) {
        // flat contiguous copy: W2[kc..kc+128) rows = 128*76 floats contiguous
        const float4* srcW = (const float4*)(W2 + (size_t)kc * F2c);
        float4* dstW = (float4*)sW;
        for (int i = tid; i < (128 * F2c) / 4; i += 256) dstW[i] = srcW[i];
        __syncthreads();

        for (int k4 = 0; k4 < 128; k4 += 4) {
            float4 hv[8];
#pragma unroll
            for (int r = 0; r < 8; r++) {
                int row = row0 + r;
                hv[r] = (row < N1c)
                      ? *(const float4*)(g_h1 + (size_t)row * F1c + kc + k4)
                      : make_float4(0.f, 0.f, 0.f, 0.f);
            }
#pragma unroll
            for (int kk = 0; kk < 4; kk++) {
                const float* wr = sW + (k4 + kk) * F2c;
                float w0 = wr[l];
                float w1 = wr[l + 32];
                float w2 = (l < 12) ? wr[l + 64] : 0.f;
#pragma unroll
                for (int r = 0; r < 8; r++) {
                    float hvv = (kk == 0) ? hv[r].x : (kk == 1) ? hv[r].y
                              : (kk == 2) ? hv[r].z : hv[r].w;
                    a0[r] = fmaf(hvv, w0, a0[r]);
                    a1[r] = fmaf(hvv, w1, a1[r]);
                    a2[r] = fmaf(hvv, w2, a2[r]);
                }
            }
        }
        __syncthreads();
    }

#pragma unroll
    for (int r = 0; r < 8; r++) {
        int row = row0 + r;
        if (row < N1c) {
            float* o = g_fs2 + (size_t)row * F2c;
            o[l] = a0[r]; o[l + 32] = a1[r];
            if (l < 12) o[l + 64] = a2[r];
        }
    }
}

// -------------------- attention projections (layer 2) -----------------------
__global__ void attn2_kernel(const float* __restrict__ al2, const float* __restrict__ ar2) {
    int idx = blockIdx.x * blockDim.x + threadIdx.x;
    if (idx >= N1c * 4) return;
    int r = idx >> 2, h = idx & 3;
    const float* f = g_fs2 + (size_t)r * F2c + h * Cc;
    float s = 0.f;
#pragma unroll
    for (int c = 0; c < Cc; c++) s = fmaf(f[c], al2[h * Cc + c], s);
    g_el2[idx] = s;
    if (r < N2c) {
        float sr = 0.f;
#pragma unroll
        for (int c = 0; c < Cc; c++) sr = fmaf(f[c], ar2[h * Cc + c], sr);
        g_er2[r * 4 + h] = sr;
    }
}

// -------------------- layer-2 edge softmax + agg + bias + head-mean ---------
__global__ __launch_bounds__(128) void agg2_kernel(const float* __restrict__ b2,
                                                   float* __restrict__ out) {
    const int d = blockIdx.x, t = threadIdx.x;
    __shared__ int   sh_src[128];
    __shared__ float sh_ex[128 * 4];
    __shared__ float sh_red[128];
    __shared__ float sh_out[80];
    const int beg = g_off2[d];
    const int deg = g_off2[d + 1] - beg;
    float4 er = *(const float4*)(g_er2 + (size_t)d * 4);

    float m0 = -1e30f, m1 = -1e30f, m2 = -1e30f, m3 = -1e30f;
    for (int i = t; i < deg; i += 128) {
        int s = g_esrc2[beg + i];
        float4 el = *(const float4*)(g_el2 + (size_t)s * 4);
        float q;
        q = el.x + er.x; q = (q > 0.f) ? q : NEG * q; m0 = fmaxf(m0, q);
        q = el.y + er.y; q = (q > 0.f) ? q : NEG * q; m1 = fmaxf(m1, q);
        q = el.z + er.z; q = (q > 0.f) ? q : NEG * q; m2 = fmaxf(m2, q);
        q = el.w + er.w; q = (q > 0.f) ? q : NEG * q; m3 = fmaxf(m3, q);
    }
    m0 = bredmax(m0, sh_red, t); m1 = bredmax(m1, sh_red, t);
    m2 = bredmax(m2, sh_red, t); m3 = bredmax(m3, sh_red, t);

    const int h = (t < F2c) ? (t / Cc) : 0;
    float acc = 0.f;
    float s0 = 0.f, s1 = 0.f, s2 = 0.f, s3 = 0.f;
    for (int base = 0; base < deg; base += 128) {
        int len = min(128, deg - base);
        if (t < len) {
            int s = g_esrc2[beg + base + t];
            float4 el = *(const float4*)(g_el2 + (size_t)s * 4);
            float q, e0, e1, e2, e3;
            q = el.x + er.x; q = (q > 0.f) ? q : NEG * q; e0 = __expf(q - m0); s0 += e0;
            q = el.y + er.y; q = (q > 0.f) ? q : NEG * q; e1 = __expf(q - m1); s1 += e1;
            q = el.z + er.z; q = (q > 0.f) ? q : NEG * q; e2 = __expf(q - m2); s2 += e2;
            q = el.w + er.w; q = (q > 0.f) ? q : NEG * q; e3 = __expf(q - m3); s3 += e3;
            sh_src[t] = s;
            sh_ex[t * 4 + 0] = e0; sh_ex[t * 4 + 1] = e1;
            sh_ex[t * 4 + 2] = e2; sh_ex[t * 4 + 3] = e3;
        }
        __syncthreads();
        if (t < F2c) {
            for (int i = 0; i < len; i++)
                acc = fmaf(sh_ex[i * 4 + h], g_fs2[(size_t)sh_src[i] * F2c + t], acc);
        }
        __syncthreads();
    }
    s0 = bredsum(s0, sh_red, t); s1 = bredsum(s1, sh_red, t);
    s2 = bredsum(s2, sh_red, t); s3 = bredsum(s3, sh_red, t);
    if (t < F2c) {
        float dn = (h == 0) ? s0 : (h == 1) ? s1 : (h == 2) ? s2 : s3;
        float v = (deg > 0) ? acc / dn : 0.f;
        sh_out[t] = v + b2[t];
    }
    __syncthreads();
    if (t < Cc)
        out[(size_t)d * Cc + t] =
            0.25f * (sh_out[t] + sh_out[t + Cc] + sh_out[t + 2 * Cc] + sh_out[t + 3 * Cc]);
}

// -------------------- launch -------------------------------------------------
extern "C" void kernel_launch(void* const* d_in, const int* in_sizes, int n_in,
                              void* d_out, int out_size) {
    const float* x   = (const float*)d_in[0];
    const int*   src1 = (const int*)d_in[1];
    const int*   dst1 = (const int*)d_in[2];
    const int*   src2 = (const int*)d_in[3];
    const int*   dst2 = (const int*)d_in[4];
    const float* W1  = (const float*)d_in[5];
    const float* al1 = (const float*)d_in[6];
    const float* ar1 = (const float*)d_in[7];
    const float* b1  = (const float*)d_in[8];
    const float* W2  = (const float*)d_in[9];
    const float* al2 = (const float*)d_in[10];
    const float* ar2 = (const float*)d_in[11];
    const float* b2  = (const float*)d_in[12];
    float* out = (float*)d_out;

    // CSR build for both graphs
    zero_kernel<<<(N1c + 255) / 256, 256>>>();
    count_kernel<<<(E1c + 255) / 256, 256>>>(dst1, E1c, 0);
    scan_kernel<<<1, 1024>>>(N1c, 0);
    scatter_kernel<<<(E1c + 255) / 256, 256>>>(dst1, src1, E1c, 0);
    count_kernel<<<(E2c + 255) / 256, 256>>>(dst2, E2c, 1);
    scan_kernel<<<1, 1024>>>(N2c, 1);
    scatter_kernel<<<(E2c + 255) / 256, 256>>>(dst2, src2, E2c, 1);

    // layer 1 (attention projections fused into GEMM1 epilogue)
    dim3 g1((N0c + 127) / 128, F1c / 128);
    gemm1_kernel<<<g1, 256>>>(x, W1, al1, ar1);
    agg1_kernel<<<N1c, 128>>>(b1);

    // layer 2
    gemm2_kernel<<<(N1c + 63) / 64, 256>>>(W2);
    attn2_kernel<<<(N1c * 4 + 255) / 256, 256>>>(al2, ar2);
    agg2_kernel<<<N2c, 128>>>(b2, out);
}

// round 14
// speedup vs baseline: 1.3972x; 1.3972x over previous
#include <cuda_runtime.h>
#include <cstdint>

// ---------------------------------------------------------------------------
// DistGAT: 2-layer GAT.
//   L1: fs1 = x @ W1 via mma.sync tf32 (+fused el/er epilogue); edge-softmax; agg -> relu -> h1
//   L2: fs2 = h1 @ W2; el/er; edge-softmax; agg -> +b2 -> mean heads
// ---------------------------------------------------------------------------

#define N0c   100000
#define N1c   25000
#define N2c   5000
#define E1c   800000
#define E2c   160000
#define INc   1024
#define F1c   512     // H*HID
#define F2c   76      // H*C
#define HIDc  128
#define Cc    19
#define NEG   0.2f

// -------------------- device scratch (static, allocation-free) --------------
__device__ float g_fs1[(size_t)N0c * F1c];   // ~205 MB
__device__ float g_el1[(size_t)N0c * 4];
__device__ float g_er1[(size_t)N1c * 4];
__device__ float g_h1 [(size_t)N1c * F1c];
__device__ float g_fs2[(size_t)N1c * F2c];
__device__ float g_el2[(size_t)N1c * 4];
__device__ float g_er2[(size_t)N2c * 4];
__device__ int   g_deg1[N1c], g_off1[N1c + 1], g_pos1[N1c], g_esrc1[E1c];
__device__ int   g_deg2[N2c], g_off2[N2c + 1], g_pos2[N2c], g_esrc2[E2c];

// -------------------- graph CSR build ---------------------------------------
__global__ void zero_kernel() {
    int i = blockIdx.x * blockDim.x + threadIdx.x;
    if (i < N1c) g_deg1[i] = 0;
    if (i < N2c) g_deg2[i] = 0;
}

__global__ void count_kernel(const int* __restrict__ dst, int n, int which) {
    int i = blockIdx.x * blockDim.x + threadIdx.x;
    if (i < n) {
        if (which) atomicAdd(&g_deg2[dst[i]], 1);
        else       atomicAdd(&g_deg1[dst[i]], 1);
    }
}

__global__ void scan_kernel(int n, int which) {
    __shared__ int sh[1024];
    __shared__ int carry;
    int* deg = which ? g_deg2 : g_deg1;
    int* off = which ? g_off2 : g_off1;
    int* pos = which ? g_pos2 : g_pos1;
    int t = threadIdx.x;
    if (t == 0) carry = 0;
    __syncthreads();
    for (int base = 0; base < n; base += 1024) {
        int i = base + t;
        int v = (i < n) ? deg[i] : 0;
        int incl = v;
        sh[t] = v;
        __syncthreads();
        for (int s = 1; s < 1024; s <<= 1) {
            int add = (t >= s) ? sh[t - s] : 0;
            __syncthreads();
            incl += add;
            sh[t] = incl;
            __syncthreads();
        }
        int c = carry;
        if (i < n) { off[i] = incl - v + c; pos[i] = incl - v + c; }
        int total = sh[1023];
        __syncthreads();
        if (t == 0) carry = c + total;
        __syncthreads();
    }
    if (t == 0) off[n] = carry;
}

__global__ void scatter_kernel(const int* __restrict__ dst, const int* __restrict__ src,
                               int n, int which) {
    int i = blockIdx.x * blockDim.x + threadIdx.x;
    if (i < n) {
        int s = src[i];
        if (which) { int p = atomicAdd(&g_pos2[dst[i]], 1); g_esrc2[p] = s; }
        else       { int p = atomicAdd(&g_pos1[dst[i]], 1); g_esrc1[p] = s; }
    }
}

// -------------------- GEMM1 via mma.sync tf32 --------------------------------
// CTA 128x128, 256 thr, warp grid 2(M)x4(N): warp tile 64x32 = 16 m16n8k8 tiles.
// BK=32 double-buffered. As [m][k] pad 36 (conflict-free a-frags), Bs [k][n]
// pad 132. W1 is [K,N] row-major == direct (k,n) indexing, no transpose.
// Fused el1/er1 epilogue (head h == blockIdx.y since HID==128 == N tile).

__device__ __forceinline__ uint32_t f2tf(float f) {
    uint32_t u;
    asm("cvt.rna.tf32.f32 %0, %1;" : "=r"(u) : "f"(f));
    return u;
}

#define ASTR 36
#define BSTR 132
#define ASZ  (128 * ASTR)          // u32 per A buffer
#define BSZ  (32 * BSTR)           // u32 per B buffer
#define SMEM_GEMM1 ((ASZ + BSZ) * 2 * 4)

__global__ __launch_bounds__(256, 1) void gemm1_tc(const float* __restrict__ A,
                                                   const float* __restrict__ W1,
                                                   const float* __restrict__ al,
                                                   const float* __restrict__ ar) {
    extern __shared__ uint32_t sm[];
    const int tid = threadIdx.x;
    const int lane = tid & 31, wid = tid >> 5;
    const int gid = lane >> 2, tig = lane & 3;
    const int wm = wid >> 2, wn = wid & 3;        // warp grid 2x4
    const int bm = blockIdx.x * 128;
    const int h  = blockIdx.y;                     // head / 128-col tile
    const int bn = h * 128;

    uint32_t* bufA[2] = {sm, sm + ASZ + BSZ};
    uint32_t* bufB[2] = {sm + ASZ, sm + 2 * ASZ + BSZ};

    float c[4][4][4];
#pragma unroll
    for (int mt = 0; mt < 4; mt++)
#pragma unroll
        for (int nt = 0; nt < 4; nt++)
#pragma unroll
            for (int j = 0; j < 4; j++) c[mt][nt][j] = 0.f;

    // staging indices (constant over k-chunks)
    const int aq = tid & 7;          // float4 slot in 32-wide k row
    const int ar0 = tid >> 3;        // A row base (it*32 + ar0)
    const int bk0 = tid >> 5;        // B k base (it*8 + bk0)
    const int bnq = tid & 31;        // B float4 slot in 128-wide n row

    float4 ga[4], gb[4];
#pragma unroll
    for (int it = 0; it < 4; it++) {
        int row = bm + it * 32 + ar0;
        ga[it] = (row < N0c) ? *(const float4*)(A + (size_t)row * INc + aq * 4)
                             : make_float4(0.f, 0.f, 0.f, 0.f);
        gb[it] = *(const float4*)(W1 + (size_t)(it * 8 + bk0) * F1c + bn + bnq * 4);
    }
    // store chunk 0
#pragma unroll
    for (int it = 0; it < 4; it++) {
        uint32_t* pa = bufA[0] + (it * 32 + ar0) * ASTR + aq * 4;
        pa[0] = f2tf(ga[it].x); pa[1] = f2tf(ga[it].y);
        pa[2] = f2tf(ga[it].z); pa[3] = f2tf(ga[it].w);
        uint32_t* pb = bufB[0] + (it * 8 + bk0) * BSTR + bnq * 4;
        pb[0] = f2tf(gb[it].x); pb[1] = f2tf(gb[it].y);
        pb[2] = f2tf(gb[it].z); pb[3] = f2tf(gb[it].w);
    }

    for (int i = 0; i < 32; i++) {
        __syncthreads();
        if (i + 1 < 32) {
            int kc = (i + 1) * 32;
#pragma unroll
            for (int it = 0; it < 4; it++) {
                int row = bm + it * 32 + ar0;
                ga[it] = (row < N0c)
                       ? *(const float4*)(A + (size_t)row * INc + kc + aq * 4)
                       : make_float4(0.f, 0.f, 0.f, 0.f);
                gb[it] = *(const float4*)(W1 + (size_t)(kc + it * 8 + bk0) * F1c + bn + bnq * 4);
            }
        }
        const uint32_t* As = bufA[i & 1];
        const uint32_t* Bs = bufB[i & 1];
#pragma unroll
        for (int kt = 0; kt < 4; kt++) {
            const int k0 = kt * 8;
            uint32_t a[4][4], b[4][2];
#pragma unroll
            for (int mt = 0; mt < 4; mt++) {
                int m = wm * 64 + mt * 16 + gid;
                a[mt][0] = As[m * ASTR + k0 + tig];
                a[mt][1] = As[(m + 8) * ASTR + k0 + tig];
                a[mt][2] = As[m * ASTR + k0 + tig + 4];
                a[mt][3] = As[(m + 8) * ASTR + k0 + tig + 4];
            }
#pragma unroll
            for (int nt = 0; nt < 4; nt++) {
                int n = wn * 32 + nt * 8 + gid;
                b[nt][0] = Bs[(k0 + tig) * BSTR + n];
                b[nt][1] = Bs[(k0 + tig + 4) * BSTR + n];
            }
#pragma unroll
            for (int mt = 0; mt < 4; mt++)
#pragma unroll
                for (int nt = 0; nt < 4; nt++)
                    asm volatile(
                        "mma.sync.aligned.m16n8k8.row.col.f32.tf32.tf32.f32 "
                        "{%0,%1,%2,%3}, {%4,%5,%6,%7}, {%8,%9}, {%0,%1,%2,%3};"
                        : "+f"(c[mt][nt][0]), "+f"(c[mt][nt][1]),
                          "+f"(c[mt][nt][2]), "+f"(c[mt][nt][3])
                        : "r"(a[mt][0]), "r"(a[mt][1]), "r"(a[mt][2]), "r"(a[mt][3]),
                          "r"(b[nt][0]), "r"(b[nt][1]));
        }
        if (i + 1 < 32) {
            int nb = (i + 1) & 1;
#pragma unroll
            for (int it = 0; it < 4; it++) {
                uint32_t* pa = bufA[nb] + (it * 32 + ar0) * ASTR + aq * 4;
                pa[0] = f2tf(ga[it].x); pa[1] = f2tf(ga[it].y);
                pa[2] = f2tf(ga[it].z); pa[3] = f2tf(ga[it].w);
                uint32_t* pb = bufB[nb] + (it * 8 + bk0) * BSTR + bnq * 4;
                pb[0] = f2tf(gb[it].x); pb[1] = f2tf(gb[it].y);
                pb[2] = f2tf(gb[it].z); pb[3] = f2tf(gb[it].w);
            }
        }
    }
    __syncthreads();

    // ---- epilogue: store fs1 + fused el/er attention dots ----
    // attention weights at this thread's 8 columns (per nt: cols 2tig, 2tig+1)
    float alw[4][2], arw[4][2];
#pragma unroll
    for (int nt = 0; nt < 4; nt++) {
        int col = h * HIDc + wn * 32 + nt * 8 + 2 * tig;
        alw[nt][0] = __ldg(al + col);     alw[nt][1] = __ldg(al + col + 1);
        arw[nt][0] = __ldg(ar + col);     arw[nt][1] = __ldg(ar + col + 1);
    }

    float* shel = (float*)sm;            // [4][128]
    float* sher = (float*)sm + 512;      // [4][128]

#pragma unroll
    for (int mt = 0; mt < 4; mt++) {
#pragma unroll
        for (int p = 0; p < 2; p++) {
            int lrow = wm * 64 + mt * 16 + p * 8 + gid;
            int row = bm + lrow;
            float pe = 0.f, pr = 0.f;
#pragma unroll
            for (int nt = 0; nt < 4; nt++) {
                float v0 = c[mt][nt][2 * p], v1 = c[mt][nt][2 * p + 1];
                pe = fmaf(v0, alw[nt][0], fmaf(v1, alw[nt][1], pe));
                pr = fmaf(v0, arw[nt][0], fmaf(v1, arw[nt][1], pr));
                if (row < N0c) {
                    float2 st = make_float2(v0, v1);
                    *(float2*)(g_fs1 + (size_t)row * F1c + bn + wn * 32 + nt * 8 + 2 * tig) = st;
                }
            }
            // reduce across the 4 tig-lanes of this quad
            pe += __shfl_xor_sync(0xffffffffu, pe, 1);
            pe += __shfl_xor_sync(0xffffffffu, pe, 2);
            pr += __shfl_xor_sync(0xffffffffu, pr, 1);
            pr += __shfl_xor_sync(0xffffffffu, pr, 2);
            if (tig == 0) { shel[wn * 128 + lrow] = pe; sher[wn * 128 + lrow] = pr; }
        }
    }
    __syncthreads();
    if (tid < 128) {
        int row = bm + tid;
        if (row < N0c) {
            float el = shel[tid] + shel[128 + tid] + shel[256 + tid] + shel[384 + tid];
            g_el1[(size_t)row * 4 + h] = el;
            if (row < N1c) {
                float er = sher[tid] + sher[128 + tid] + sher[256 + tid] + sher[384 + tid];
                g_er1[(size_t)row * 4 + h] = er;
            }
        }
    }
}

// -------------------- block reductions --------------------------------------
__device__ __forceinline__ float bredmax(float v, float* sh, int t) {
    sh[t] = v; __syncthreads();
#pragma unroll
    for (int s = 64; s > 0; s >>= 1) { if (t < s) sh[t] = fmaxf(sh[t], sh[t + s]); __syncthreads(); }
    float r = sh[0]; __syncthreads(); return r;
}
__device__ __forceinline__ float bredsum(float v, float* sh, int t) {
    sh[t] = v; __syncthreads();
#pragma unroll
    for (int s = 64; s > 0; s >>= 1) { if (t < s) sh[t] = sh[t] + sh[t + s]; __syncthreads(); }
    float r = sh[0]; __syncthreads(); return r;
}

// -------------------- layer-1 edge softmax + aggregation + relu -------------
__global__ __launch_bounds__(128) void agg1_kernel(const float* __restrict__ b1) {
    const int d = blockIdx.x, t = threadIdx.x;
    __shared__ int    sh_src[128];
    __shared__ float4 sh_ex[128];
    __shared__ float  sh_red[128];
    const int beg = g_off1[d];
    const int deg = g_off1[d + 1] - beg;
    float4 er = *(const float4*)(g_er1 + (size_t)d * 4);

    float m0 = -1e30f, m1 = -1e30f, m2 = -1e30f, m3 = -1e30f;
    for (int i = t; i < deg; i += 128) {
        int s = g_esrc1[beg + i];
        float4 el = *(const float4*)(g_el1 + (size_t)s * 4);
        float q;
        q = el.x + er.x; q = (q > 0.f) ? q : NEG * q; m0 = fmaxf(m0, q);
        q = el.y + er.y; q = (q > 0.f) ? q : NEG * q; m1 = fmaxf(m1, q);
        q = el.z + er.z; q = (q > 0.f) ? q : NEG * q; m2 = fmaxf(m2, q);
        q = el.w + er.w; q = (q > 0.f) ? q : NEG * q; m3 = fmaxf(m3, q);
    }
    m0 = bredmax(m0, sh_red, t); m1 = bredmax(m1, sh_red, t);
    m2 = bredmax(m2, sh_red, t); m3 = bredmax(m3, sh_red, t);

    float a0 = 0.f, a1 = 0.f, a2 = 0.f, a3 = 0.f;
    float s0 = 0.f, s1 = 0.f, s2 = 0.f, s3 = 0.f;
    for (int base = 0; base < deg; base += 128) {
        int len = min(128, deg - base);
        if (t < len) {
            int s = g_esrc1[beg + base + t];
            float4 el = *(const float4*)(g_el1 + (size_t)s * 4);
            float4 ex; float q;
            q = el.x + er.x; q = (q > 0.f) ? q : NEG * q; ex.x = __expf(q - m0); s0 += ex.x;
            q = el.y + er.y; q = (q > 0.f) ? q : NEG * q; ex.y = __expf(q - m1); s1 += ex.y;
            q = el.z + er.z; q = (q > 0.f) ? q : NEG * q; ex.z = __expf(q - m2); s2 += ex.z;
            q = el.w + er.w; q = (q > 0.f) ? q : NEG * q; ex.w = __expf(q - m3); s3 += ex.w;
            sh_src[t] = s; sh_ex[t] = ex;
        }
        __syncthreads();
#pragma unroll 4
        for (int i = 0; i < len; i++) {
            const float* r = g_fs1 + (size_t)sh_src[i] * F1c + t;
            float4 ex = sh_ex[i];
            a0 = fmaf(ex.x, r[0],   a0);
            a1 = fmaf(ex.y, r[128], a1);
            a2 = fmaf(ex.z, r[256], a2);
            a3 = fmaf(ex.w, r[384], a3);
        }
        __syncthreads();
    }
    s0 = bredsum(s0, sh_red, t); s1 = bredsum(s1, sh_red, t);
    s2 = bredsum(s2, sh_red, t); s3 = bredsum(s3, sh_red, t);
    float i0 = (deg > 0) ? 1.f / s0 : 0.f;
    float i1 = (deg > 0) ? 1.f / s1 : 0.f;
    float i2 = (deg > 0) ? 1.f / s2 : 0.f;
    float i3 = (deg > 0) ? 1.f / s3 : 0.f;
    size_t o = (size_t)d * F1c + t;
    g_h1[o +   0] = fmaxf(fmaf(a0, i0, b1[t +   0]), 0.f);
    g_h1[o + 128] = fmaxf(fmaf(a1, i1, b1[t + 128]), 0.f);
    g_h1[o + 256] = fmaxf(fmaf(a2, i2, b1[t + 256]), 0.f);
    g_h1[o + 384] = fmaxf(fmaf(a3, i3, b1[t + 384]), 0.f);
}

// -------------------- GEMM2: fs2 = h1 @ W2  (25000 x 512 x 76) --------------
__global__ __launch_bounds__(256) void gemm2_kernel(const float* __restrict__ W2) {
    __shared__ float sW[128 * F2c];   // 38 KB
    const int tid = threadIdx.x;
    const int l = tid & 31;
    const int w = tid >> 5;
    const int row0 = blockIdx.x * 64 + w * 8;

    float a0[8], a1[8], a2[8];
#pragma unroll
    for (int r = 0; r < 8; r++) { a0[r] = 0.f; a1[r] = 0.f; a2[r] = 0.f; }

    for (int kc = 0; kc < F1c; kc += 128) {
        const float4* srcW = (const float4*)(W2 + (size_t)kc * F2c);
        float4* dstW = (float4*)sW;
        for (int i = tid; i < (128 * F2c) / 4; i += 256) dstW[i] = srcW[i];
        __syncthreads();

        for (int k4 = 0; k4 < 128; k4 += 4) {
            float4 hv[8];
#pragma unroll
            for (int r = 0; r < 8; r++) {
                int row = row0 + r;
                hv[r] = (row < N1c)
                      ? *(const float4*)(g_h1 + (size_t)row * F1c + kc + k4)
                      : make_float4(0.f, 0.f, 0.f, 0.f);
            }
#pragma unroll
            for (int kk = 0; kk < 4; kk++) {
                const float* wr = sW + (k4 + kk) * F2c;
                float w0 = wr[l];
                float w1 = wr[l + 32];
                float w2 = (l < 12) ? wr[l + 64] : 0.f;
#pragma unroll
                for (int r = 0; r < 8; r++) {
                    float hvv = (kk == 0) ? hv[r].x : (kk == 1) ? hv[r].y
                              : (kk == 2) ? hv[r].z : hv[r].w;
                    a0[r] = fmaf(hvv, w0, a0[r]);
                    a1[r] = fmaf(hvv, w1, a1[r]);
                    a2[r] = fmaf(hvv, w2, a2[r]);
                }
            }
        }
        __syncthreads();
    }

#pragma unroll
    for (int r = 0; r < 8; r++) {
        int row = row0 + r;
        if (row < N1c) {
            float* o = g_fs2 + (size_t)row * F2c;
            o[l] = a0[r]; o[l + 32] = a1[r];
            if (l < 12) o[l + 64] = a2[r];
        }
    }
}

// -------------------- attention projections (layer 2) -----------------------
__global__ void attn2_kernel(const float* __restrict__ al2, const float* __restrict__ ar2) {
    int idx = blockIdx.x * blockDim.x + threadIdx.x;
    if (idx >= N1c * 4) return;
    int r = idx >> 2, h = idx & 3;
    const float* f = g_fs2 + (size_t)r * F2c + h * Cc;
    float s = 0.f;
#pragma unroll
    for (int c = 0; c < Cc; c++) s = fmaf(f[c], al2[h * Cc + c], s);
    g_el2[idx] = s;
    if (r < N2c) {
        float sr = 0.f;
#pragma unroll
        for (int c = 0; c < Cc; c++) sr = fmaf(f[c], ar2[h * Cc + c], sr);
        g_er2[r * 4 + h] = sr;
    }
}

// -------------------- layer-2 edge softmax + agg + bias + head-mean ---------
__global__ __launch_bounds__(128) void agg2_kernel(const float* __restrict__ b2,
                                                   float* __restrict__ out) {
    const int d = blockIdx.x, t = threadIdx.x;
    __shared__ int   sh_src[128];
    __shared__ float sh_ex[128 * 4];
    __shared__ float sh_red[128];
    __shared__ float sh_out[80];
    const int beg = g_off2[d];
    const int deg = g_off2[d + 1] - beg;
    float4 er = *(const float4*)(g_er2 + (size_t)d * 4);

    float m0 = -1e30f, m1 = -1e30f, m2 = -1e30f, m3 = -1e30f;
    for (int i = t; i < deg; i += 128) {
        int s = g_esrc2[beg + i];
        float4 el = *(const float4*)(g_el2 + (size_t)s * 4);
        float q;
        q = el.x + er.x; q = (q > 0.f) ? q : NEG * q; m0 = fmaxf(m0, q);
        q = el.y + er.y; q = (q > 0.f) ? q : NEG * q; m1 = fmaxf(m1, q);
        q = el.z + er.z; q = (q > 0.f) ? q : NEG * q; m2 = fmaxf(m2, q);
        q = el.w + er.w; q = (q > 0.f) ? q : NEG * q; m3 = fmaxf(m3, q);
    }
    m0 = bredmax(m0, sh_red, t); m1 = bredmax(m1, sh_red, t);
    m2 = bredmax(m2, sh_red, t); m3 = bredmax(m3, sh_red, t);

    const int h = (t < F2c) ? (t / Cc) : 0;
    float acc = 0.f;
    float s0 = 0.f, s1 = 0.f, s2 = 0.f, s3 = 0.f;
    for (int base = 0; base < deg; base += 128) {
        int len = min(128, deg - base);
        if (t < len) {
            int s = g_esrc2[beg + base + t];
            float4 el = *(const float4*)(g_el2 + (size_t)s * 4);
            float q, e0, e1, e2, e3;
            q = el.x + er.x; q = (q > 0.f) ? q : NEG * q; e0 = __expf(q - m0); s0 += e0;
            q = el.y + er.y; q = (q > 0.f) ? q : NEG * q; e1 = __expf(q - m1); s1 += e1;
            q = el.z + er.z; q = (q > 0.f) ? q : NEG * q; e2 = __expf(q - m2); s2 += e2;
            q = el.w + er.w; q = (q > 0.f) ? q : NEG * q; e3 = __expf(q - m3); s3 += e3;
            sh_src[t] = s;
            sh_ex[t * 4 + 0] = e0; sh_ex[t * 4 + 1] = e1;
            sh_ex[t * 4 + 2] = e2; sh_ex[t * 4 + 3] = e3;
        }
        __syncthreads();
        if (t < F2c) {
            for (int i = 0; i < len; i++)
                acc = fmaf(sh_ex[i * 4 + h], g_fs2[(size_t)sh_src[i] * F2c + t], acc);
        }
        __syncthreads();
    }
    s0 = bredsum(s0, sh_red, t); s1 = bredsum(s1, sh_red, t);
    s2 = bredsum(s2, sh_red, t); s3 = bredsum(s3, sh_red, t);
    if (t < F2c) {
        float dn = (h == 0) ? s0 : (h == 1) ? s1 : (h == 2) ? s2 : s3;
        float v = (deg > 0) ? acc / dn : 0.f;
        sh_out[t] = v + b2[t];
    }
    __syncthreads();
    if (t < Cc)
        out[(size_t)d * Cc + t] =
            0.25f * (sh_out[t] + sh_out[t + Cc] + sh_out[t + 2 * Cc] + sh_out[t + 3 * Cc]);
}

// -------------------- launch -------------------------------------------------
extern "C" void kernel_launch(void* const* d_in, const int* in_sizes, int n_in,
                              void* d_out, int out_size) {
    const float* x   = (const float*)d_in[0];
    const int*   src1 = (const int*)d_in[1];
    const int*   dst1 = (const int*)d_in[2];
    const int*   src2 = (const int*)d_in[3];
    const int*   dst2 = (const int*)d_in[4];
    const float* W1  = (const float*)d_in[5];
    const float* al1 = (const float*)d_in[6];
    const float* ar1 = (const float*)d_in[7];
    const float* b1  = (const float*)d_in[8];
    const float* W2  = (const float*)d_in[9];
    const float* al2 = (const float*)d_in[10];
    const float* ar2 = (const float*)d_in[11];
    const float* b2  = (const float*)d_in[12];
    float* out = (float*)d_out;

    cudaFuncSetAttribute(gemm1_tc, cudaFuncAttributeMaxDynamicSharedMemorySize, SMEM_GEMM1);

    // CSR build for both graphs
    zero_kernel<<<(N1c + 255) / 256, 256>>>();
    count_kernel<<<(E1c + 255) / 256, 256>>>(dst1, E1c, 0);
    scan_kernel<<<1, 1024>>>(N1c, 0);
    scatter_kernel<<<(E1c + 255) / 256, 256>>>(dst1, src1, E1c, 0);
    count_kernel<<<(E2c + 255) / 256, 256>>>(dst2, E2c, 1);
    scan_kernel<<<1, 1024>>>(N2c, 1);
    scatter_kernel<<<(E2c + 255) / 256, 256>>>(dst2, src2, E2c, 1);

    // layer 1: tensor-core tf32 GEMM (+fused attn proj), aggregate
    dim3 g1((N0c + 127) / 128, 4);
    gemm1_tc<<<g1, 256, SMEM_GEMM1>>>(x, W1, al1, ar1);
    agg1_kernel<<<N1c, 128>>>(b1);

    // layer 2
    gemm2_kernel<<<(N1c + 63) / 64, 256>>>(W2);
    attn2_kernel<<<(N1c * 4 + 255) / 256, 256>>>(al2, ar2);
    agg2_kernel<<<N2c, 128>>>(b2, out);
}